// round 1
// baseline (speedup 1.0000x reference)
#include <cuda_runtime.h>
#include <math.h>

#define NB_MAX 64
#define NAA 5
#define NCC 13
#define NHH 19
#define NWW 19
#define NPIX 361
#define NANCH 1805
#define MAXOBJ 50
#define NCH 130   /* NA*(13+NC) */

// scratch (no allocations allowed)
__device__ double g_accum;
__device__ int    g_winner[NB_MAX * NPIX];
__device__ float  g_gs[NB_MAX * MAXOBJ * 12];     // corner coords pre-scaled by (640,480)
__device__ float  g_tvals[NB_MAX * MAXOBJ * 12];  // coord-regression targets
__device__ float  g_tconf[NB_MAX * MAXOBJ];       // tconf_v
__device__ int    g_clsl[NB_MAX * MAXOBJ];
__device__ int    g_nv[NB_MAX];

__device__ __forceinline__ float sigmoidf_fast(float x) {
    return __fdividef(1.f, 1.f + __expf(-x));
}
__device__ __forceinline__ float sqrt_approx(float x) {
    float r; asm("sqrt.approx.f32 %0, %1;" : "=f"(r) : "f"(x)); return r;
}

// 1/(e^2 - 1) ; final conf scale applied after max (positive scaling commutes with max)
#define INV_CONF0 0.15651764274966568f

// ---------------------------------------------------------------------------
// Kernel 1: parse target, compute per-object data + winner table (one block/batch)
// ---------------------------------------------------------------------------
__global__ void prep_kernel(const float* __restrict__ out,
                            const float* __restrict__ tgt) {
    int b = blockIdx.x;
    int t = threadIdx.x;
    __shared__ int snv;
    __shared__ int scell[MAXOBJ];

    if (t == 0) {
        if (b == 0) g_accum = 0.0;
        // valid = cumprod(g0 != 0): first zero truncates
        int n = 0;
        while (n < MAXOBJ && tgt[(b * MAXOBJ + n) * 15 + 1] != 0.f) n++;
        snv = n;
        g_nv[b] = n;
    }
    __syncthreads();
    int nv = snv;

    for (int c = t; c < NPIX; c += blockDim.x) g_winner[b * NPIX + c] = -1;

    if (t < MAXOBJ) {
        const float* row = tgt + (size_t)(b * MAXOBJ + t) * 15;
        float cls = row[0];
        float g[12];
        #pragma unroll
        for (int k = 0; k < 12; k++) g[k] = row[1 + k];

        int gi = (int)floorf(g[0] * 19.f);
        int gj = (int)floorf(g[1] * 19.f);
        scell[t] = gj * NWW + gi;

        float* gs = g_gs + (size_t)(b * MAXOBJ + t) * 12;
        #pragma unroll
        for (int c = 0; c < 6; c++) {
            gs[2 * c]     = g[2 * c] * 640.f;
            gs[2 * c + 1] = g[2 * c + 1] * 480.f;
        }
        float* tv = g_tvals + (size_t)(b * MAXOBJ + t) * 12;
        tv[0] = g[0] * 19.f - (float)gi;
        tv[1] = g[1] * 19.f - (float)gj;
        #pragma unroll
        for (int k = 1; k < 6; k++) {
            tv[2 * k]     = (g[2 * k]     - g[0]) * 19.f;
            tv[2 * k + 1] = (g[2 * k + 1] - g[1]) * 19.f;
        }
        g_clsl[b * MAXOBJ + t] = (int)cls;

        // tconf_v = conf(b, obj, anchor0 @ its own cell)
        float tcv = 0.f;
        if (t < nv) {
            int r  = scell[t];
            int jj = gj, ii = gi;
            const float* base = out + (size_t)b * NCH * NPIX + r;   // a = 0
            float ch[12];
            #pragma unroll
            for (int c = 0; c < 12; c++) ch[c] = base[(size_t)c * NPIX];
            float x0 = sigmoidf_fast(ch[0]);
            float y0 = sigmoidf_fast(ch[1]);
            const float SX = 640.f / 19.f, SY = 480.f / 19.f;
            float px[6], py[6];
            px[0] = (x0 + (float)ii) * SX;
            py[0] = (y0 + (float)jj) * SY;
            #pragma unroll
            for (int k = 1; k < 6; k++) {
                px[k] = fmaf(ch[2 * k],     SX, px[0]);
                py[k] = fmaf(ch[2 * k + 1], SY, py[0]);
            }
            float acc = 0.f;
            #pragma unroll
            for (int c = 0; c < 6; c++) {
                float dx = g[2 * c] * 640.f - px[c];
                float dy = g[2 * c + 1] * 480.f - py[c];
                float d2 = fmaf(dy, dy, dx * dx);
                if (d2 < 6400.f) {
                    float dist = sqrt_approx(d2);
                    acc += (__expf(fmaf(dist, -0.025f, 2.f)) - 1.f);
                }
            }
            tcv = acc * (INV_CONF0 / 6.f);
        }
        g_tconf[b * MAXOBJ + t] = tcv;
    }
    __syncthreads();

    if (t == 0) {
        // scan semantics: later valid object overwrites same cell
        for (int q = 0; q < nv; q++) g_winner[b * NPIX + scell[q]] = q;
    }
}

// ---------------------------------------------------------------------------
// Kernel 2: per-anchor fused loss (conf-max over objects + all three losses)
// ---------------------------------------------------------------------------
__global__ void __launch_bounds__(128) main_kernel(const float* __restrict__ out) {
    int b = blockIdx.y;
    int A = blockIdx.x * blockDim.x + threadIdx.x;

    __shared__ float sg[MAXOBJ * 12];
    __shared__ int   snv;
    __shared__ float swsum[4];

    if (threadIdx.x == 0) snv = g_nv[b];
    __syncthreads();
    int nv = snv;
    for (int k = threadIdx.x; k < nv * 12; k += blockDim.x)
        sg[k] = g_gs[(size_t)b * MAXOBJ * 12 + k];
    __syncthreads();

    float lsum = 0.f;
    if (A < NANCH) {
        int a = A / NPIX;
        int r = A - a * NPIX;
        int j = r / NWW;
        int i = r - j * NWW;

        const float* base = out + ((size_t)b * NCH + a * 26) * NPIX + r;
        float ch[13];
        #pragma unroll
        for (int c = 0; c < 13; c++) ch[c] = base[(size_t)c * NPIX];

        float x0 = sigmoidf_fast(ch[0]);
        float y0 = sigmoidf_fast(ch[1]);
        const float SX = 640.f / 19.f, SY = 480.f / 19.f;
        float px[6], py[6];
        px[0] = (x0 + (float)i) * SX;
        py[0] = (y0 + (float)j) * SY;
        #pragma unroll
        for (int k = 1; k < 6; k++) {
            px[k] = fmaf(ch[2 * k],     SX, px[0]);
            py[k] = fmaf(ch[2 * k + 1], SY, py[0]);
        }

        // running max of (unnormalized) conf over valid objects
        float m = 0.f;
        for (int t = 0; t < nv; t++) {
            float acc = 0.f;
            #pragma unroll
            for (int c = 0; c < 6; c++) {
                float dx = sg[t * 12 + 2 * c]     - px[c];
                float dy = sg[t * 12 + 2 * c + 1] - py[c];
                float d2 = fmaf(dy, dy, dx * dx);
                if (d2 < 6400.f) {
                    float dist = sqrt_approx(d2);
                    acc += (__expf(fmaf(dist, -0.025f, 2.f)) - 1.f);
                }
            }
            m = fmaxf(m, acc);
        }
        m *= (INV_CONF0 / 6.f);   // cur_conf at this anchor

        float conf = sigmoidf_fast(ch[12]);
        float mask = (m < 0.4f) ? 1.f : 0.f;
        float tc = 0.f;

        if (a == 0) {
            int w = g_winner[b * NPIX + r];
            if (w >= 0) {
                mask = 5.f;  // OBJECT_SCALE
                tc = g_tconf[b * MAXOBJ + w];

                // coord loss (anchor 0, winner cell)
                const float* tv = g_tvals + (size_t)(b * MAXOBJ + w) * 12;
                float d0 = x0 - tv[0];
                float d1 = y0 - tv[1];
                float cs = fmaf(d1, d1, d0 * d0);
                #pragma unroll
                for (int k = 2; k < 12; k++) {
                    float d = ch[k] - tv[k];
                    cs = fmaf(d, d, cs);
                }
                lsum += 0.5f * cs;

                // class NLL
                const float* cbase = base + (size_t)13 * NPIX;
                float lg[NCC];
                float mx = -1e30f;
                #pragma unroll
                for (int c = 0; c < NCC; c++) {
                    lg[c] = cbase[(size_t)c * NPIX];
                    mx = fmaxf(mx, lg[c]);
                }
                float se = 0.f;
                #pragma unroll
                for (int c = 0; c < NCC; c++) se += __expf(lg[c] - mx);
                float lse = mx + __logf(se);
                int tcls = g_clsl[b * MAXOBJ + w];
                lsum += lse - lg[tcls];
            }
        }
        float cd = conf - tc;
        lsum += 0.5f * mask * cd * cd;
    }

    // block reduce (float intra-warp, double across blocks)
    #pragma unroll
    for (int off = 16; off > 0; off >>= 1)
        lsum += __shfl_down_sync(0xffffffffu, lsum, off);
    int wid = threadIdx.x >> 5;
    if ((threadIdx.x & 31) == 0) swsum[wid] = lsum;
    __syncthreads();
    if (threadIdx.x == 0) {
        double s = 0.0;
        #pragma unroll
        for (int w = 0; w < 4; w++) s += (double)swsum[w];
        atomicAdd(&g_accum, s);
    }
}

__global__ void finish_kernel(float* d_out) {
    d_out[0] = (float)g_accum;
}

extern "C" void kernel_launch(void* const* d_in, const int* in_sizes, int n_in,
                              void* d_out, int out_size) {
    const float* out = (const float*)d_in[0];
    const float* tgt = (const float*)d_in[1];
    int nB = in_sizes[0] / (NCH * NPIX);   // 64 for the reference shapes

    prep_kernel<<<nB, 64>>>(out, tgt);
    dim3 grid((NANCH + 127) / 128, nB);
    main_kernel<<<grid, 128>>>(out);
    finish_kernel<<<1, 1>>>((float*)d_out);
}

// round 2
// speedup vs baseline: 1.3160x; 1.3160x over previous
#include <cuda_runtime.h>
#include <math.h>

#define NB_MAX 64
#define NAA 5
#define NCC 13
#define NPIX 361
#define NANCH 1805
#define MAXOBJ 50
#define NCH 130      /* NA*(13+NC) */
#define NBLK 15      /* ceil(1805/128) */

__device__ double g_part[NB_MAX * NBLK];

__device__ __forceinline__ float sigmoidf_fast(float x) {
    return __fdividef(1.f, 1.f + __expf(-x));
}
__device__ __forceinline__ float sqrt_approx(float x) {
    float r; asm("sqrt.approx.f32 %0, %1;" : "=f"(r) : "f"(x)); return r;
}

// 1/(e^2 - 1); applied after the max (positive scale commutes with max)
#define INV_CONF0 0.15651764274966568f

// ---------------------------------------------------------------------------
// Fused kernel: per-block redundant target prep + per-anchor loss
// grid = (NBLK, nB), block = 128
// ---------------------------------------------------------------------------
__global__ void __launch_bounds__(128) fused_kernel(const float* __restrict__ out,
                                                    const float* __restrict__ tgt) {
    int b   = blockIdx.y;
    int bx  = blockIdx.x;
    int tid = threadIdx.x;
    int A0  = bx * 128;

    __shared__ float2 sg[MAXOBJ * 6];      // scaled object corners
    __shared__ float  stv[MAXOBJ * 12];    // coord targets
    __shared__ float  stconf[MAXOBJ];
    __shared__ int    scls[MAXOBJ];
    __shared__ int    scell[MAXOBJ];
    __shared__ short  swin[NPIX];
    __shared__ int    snv;
    __shared__ int    swmin[4];
    __shared__ float  swsum[4];

    // ---- per-block target prep (redundant across bx; L2-resident) ----
    for (int c = tid; c < NPIX; c += 128) swin[c] = -1;

    float g[12]; float cls = 0.f;
    int gi = 0, gj = 0;
    bool has = (tid < MAXOBJ);
    if (has) {
        const float* row = tgt + (size_t)(b * MAXOBJ + tid) * 15;
        cls = row[0];
        #pragma unroll
        for (int k = 0; k < 12; k++) g[k] = row[1 + k];
        gi = (int)floorf(g[0] * 19.f);
        gj = (int)floorf(g[1] * 19.f);
        scell[tid] = gj * 19 + gi;
        #pragma unroll
        for (int c = 0; c < 6; c++)
            sg[tid * 6 + c] = make_float2(g[2 * c] * 640.f, g[2 * c + 1] * 480.f);
        float* tv = stv + tid * 12;
        tv[0] = g[0] * 19.f - (float)gi;
        tv[1] = g[1] * 19.f - (float)gj;
        #pragma unroll
        for (int k = 1; k < 6; k++) {
            tv[2 * k]     = (g[2 * k]     - g[0]) * 19.f;
            tv[2 * k + 1] = (g[2 * k + 1] - g[1]) * 19.f;
        }
        scls[tid] = (int)cls;
    }

    // nv = index of first object with g0 == 0 (cumprod validity)
    int cand = (has && g[0] == 0.f) ? tid : MAXOBJ;
    #pragma unroll
    for (int off = 16; off > 0; off >>= 1)
        cand = min(cand, __shfl_down_sync(0xffffffffu, cand, off));
    if ((tid & 31) == 0) swmin[tid >> 5] = cand;
    __syncthreads();
    if (tid == 0) {
        int nv = min(min(swmin[0], swmin[1]), min(swmin[2], swmin[3]));
        snv = nv;
        // scan semantics: later valid object overwrites same cell
        for (int q = 0; q < nv; q++) swin[scell[q]] = (short)q;
    }
    __syncthreads();
    int nv = snv;

    // tconf_v only needed by blocks covering anchor 0
    if (A0 < NPIX && tid < nv) {
        int r = scell[tid];
        const float* base = out + (size_t)b * NCH * NPIX + r;   // anchor 0
        float ch[12];
        #pragma unroll
        for (int c = 0; c < 12; c++) ch[c] = base[(size_t)c * NPIX];
        float x0 = sigmoidf_fast(ch[0]);
        float y0 = sigmoidf_fast(ch[1]);
        const float SX = 640.f / 19.f, SY = 480.f / 19.f;
        float px[6], py[6];
        px[0] = (x0 + (float)gi) * SX;
        py[0] = (y0 + (float)gj) * SY;
        #pragma unroll
        for (int k = 1; k < 6; k++) {
            px[k] = fmaf(ch[2 * k],     SX, px[0]);
            py[k] = fmaf(ch[2 * k + 1], SY, py[0]);
        }
        float acc = 0.f;
        #pragma unroll
        for (int c = 0; c < 6; c++) {
            float dx = g[2 * c] * 640.f - px[c];
            float dy = g[2 * c + 1] * 480.f - py[c];
            float d2 = fmaf(dy, dy, dx * dx);
            if (d2 < 6400.f) {
                float dist = sqrt_approx(d2);
                acc += (__expf(fmaf(dist, -0.025f, 2.f)) - 1.f);
            }
        }
        stconf[tid] = acc * (INV_CONF0 / 6.f);
    }
    __syncthreads();

    // ---- per-anchor loss ----
    float lsum = 0.f;
    int A = A0 + tid;
    if (A < NANCH) {
        int a = A / NPIX;
        int r = A - a * NPIX;
        int j = r / 19;
        int i = r - j * 19;

        const float* base = out + ((size_t)b * NCH + a * 26) * NPIX + r;
        float ch[13];
        #pragma unroll
        for (int c = 0; c < 13; c++) ch[c] = base[(size_t)c * NPIX];

        float x0 = sigmoidf_fast(ch[0]);
        float y0 = sigmoidf_fast(ch[1]);
        const float SX = 640.f / 19.f, SY = 480.f / 19.f;
        float px[6], py[6];
        px[0] = (x0 + (float)i) * SX;
        py[0] = (y0 + (float)j) * SY;
        #pragma unroll
        for (int k = 1; k < 6; k++) {
            px[k] = fmaf(ch[2 * k],     SX, px[0]);
            py[k] = fmaf(ch[2 * k + 1], SY, py[0]);
        }

        float m = 0.f;
        for (int t = 0; t < nv; t++) {
            float acc = 0.f;
            #pragma unroll
            for (int c = 0; c < 6; c++) {
                float2 gc = sg[t * 6 + c];
                float dx = gc.x - px[c];
                float dy = gc.y - py[c];
                float d2 = fmaf(dy, dy, dx * dx);
                if (d2 < 6400.f) {
                    float dist = sqrt_approx(d2);
                    acc += (__expf(fmaf(dist, -0.025f, 2.f)) - 1.f);
                }
            }
            m = fmaxf(m, acc);
        }
        m *= (INV_CONF0 / 6.f);

        float conf = sigmoidf_fast(ch[12]);
        float mask = (m < 0.4f) ? 1.f : 0.f;
        float tc = 0.f;

        if (a == 0) {
            int w = swin[r];
            if (w >= 0) {
                mask = 5.f;   // OBJECT_SCALE
                tc = stconf[w];

                const float* tv = stv + w * 12;
                float d0 = x0 - tv[0];
                float d1 = y0 - tv[1];
                float cs = fmaf(d1, d1, d0 * d0);
                #pragma unroll
                for (int k = 2; k < 12; k++) {
                    float d = ch[k] - tv[k];
                    cs = fmaf(d, d, cs);
                }
                lsum += 0.5f * cs;

                const float* cbase = base + (size_t)13 * NPIX;
                float lg[NCC];
                float mx = -1e30f;
                #pragma unroll
                for (int c = 0; c < NCC; c++) {
                    lg[c] = cbase[(size_t)c * NPIX];
                    mx = fmaxf(mx, lg[c]);
                }
                float se = 0.f;
                #pragma unroll
                for (int c = 0; c < NCC; c++) se += __expf(lg[c] - mx);
                float lse = mx + __logf(se);
                lsum += lse - lg[scls[w]];
            }
        }
        float cd = conf - tc;
        lsum += 0.5f * mask * cd * cd;
    }

    // block reduce -> per-block partial (deterministic, no zero-init needed)
    #pragma unroll
    for (int off = 16; off > 0; off >>= 1)
        lsum += __shfl_down_sync(0xffffffffu, lsum, off);
    if ((tid & 31) == 0) swsum[tid >> 5] = lsum;
    __syncthreads();
    if (tid == 0) {
        double s = 0.0;
        #pragma unroll
        for (int w = 0; w < 4; w++) s += (double)swsum[w];
        g_part[b * NBLK + bx] = s;
    }
}

// ---------------------------------------------------------------------------
// Reduce partials -> scalar
// ---------------------------------------------------------------------------
__global__ void __launch_bounds__(256) finish_kernel(float* d_out, int n) {
    __shared__ double sw[8];
    double s = 0.0;
    for (int k = threadIdx.x; k < n; k += 256) s += g_part[k];
    #pragma unroll
    for (int off = 16; off > 0; off >>= 1)
        s += __shfl_down_sync(0xffffffffu, s, off);
    if ((threadIdx.x & 31) == 0) sw[threadIdx.x >> 5] = s;
    __syncthreads();
    if (threadIdx.x == 0) {
        double t = 0.0;
        #pragma unroll
        for (int w = 0; w < 8; w++) t += sw[w];
        d_out[0] = (float)t;
    }
}

extern "C" void kernel_launch(void* const* d_in, const int* in_sizes, int n_in,
                              void* d_out, int out_size) {
    const float* out = (const float*)d_in[0];
    const float* tgt = (const float*)d_in[1];
    int nB = in_sizes[0] / (NCH * NPIX);

    dim3 grid(NBLK, nB);
    fused_kernel<<<grid, 128>>>(out, tgt);
    finish_kernel<<<1, 256>>>((float*)d_out, nB * NBLK);
}

// round 3
// speedup vs baseline: 1.3866x; 1.0536x over previous
#include <cuda_runtime.h>
#include <math.h>

#define NAA 5
#define NCC 13
#define NPIX 361
#define MAXOBJ 50
#define NCH 130         /* NA*(13+NC) */
#define TILES 15        /* 3 x-tiles(8) * 5 y-tiles(4) covering 19x19 */
#define WPB   75        /* NAA * TILES warps per batch */
#define BLKS_PB 19      /* ceil(75/4) blocks per batch, 128 thr */

__device__ double g_accum = 0.0;
__device__ int    g_done  = 0;

__device__ __forceinline__ float sigmoidf_fast(float x) {
    return __fdividef(1.f, 1.f + __expf(-x));
}
__device__ __forceinline__ float sqrt_approx(float x) {
    float r; asm("sqrt.approx.f32 %0, %1;" : "=f"(r) : "f"(x)); return r;
}

#define INV_CONF0 0.15651764274966568f   /* 1/(e^2-1) */

__global__ void __launch_bounds__(128) fused_kernel(const float* __restrict__ out,
                                                    const float* __restrict__ tgt,
                                                    float* __restrict__ d_out,
                                                    int n_blocks) {
    int b   = blockIdx.y;
    int bx  = blockIdx.x;
    int tid = threadIdx.x;

    __shared__ float2 sg[MAXOBJ * 6];
    __shared__ float  stv[MAXOBJ * 12];
    __shared__ float  stconf[MAXOBJ];
    __shared__ int    scls[MAXOBJ];
    __shared__ int    scell[MAXOBJ];
    __shared__ short  swin[NPIX];
    __shared__ int    snv;
    __shared__ int    swmin[4];
    __shared__ float  swsum[4];

    bool tgt_blk = (bx < 4);   // blocks containing anchor-0 warps (W<15)

    if (tgt_blk)
        for (int c = tid; c < NPIX; c += 128) swin[c] = -1;

    // ---- per-block target prep ----
    float g[12];
    int gi = 0, gj = 0;
    bool has = (tid < MAXOBJ);
    if (has) {
        const float* row = tgt + (size_t)(b * MAXOBJ + tid) * 15;
        float cls = row[0];
        #pragma unroll
        for (int k = 0; k < 12; k++) g[k] = row[1 + k];
        gi = (int)floorf(g[0] * 19.f);
        gj = (int)floorf(g[1] * 19.f);
        scell[tid] = gj * 19 + gi;
        #pragma unroll
        for (int c = 0; c < 6; c++)
            sg[tid * 6 + c] = make_float2(g[2 * c] * 640.f, g[2 * c + 1] * 480.f);
        if (tgt_blk) {
            float* tv = stv + tid * 12;
            tv[0] = g[0] * 19.f - (float)gi;
            tv[1] = g[1] * 19.f - (float)gj;
            #pragma unroll
            for (int k = 1; k < 6; k++) {
                tv[2 * k]     = (g[2 * k]     - g[0]) * 19.f;
                tv[2 * k + 1] = (g[2 * k + 1] - g[1]) * 19.f;
            }
            scls[tid] = (int)cls;
        }
    }

    int cand = (has && g[0] == 0.f) ? tid : MAXOBJ;
    #pragma unroll
    for (int off = 16; off > 0; off >>= 1)
        cand = min(cand, __shfl_down_sync(0xffffffffu, cand, off));
    if ((tid & 31) == 0) swmin[tid >> 5] = cand;
    __syncthreads();
    if (tid == 0) {
        int nv = min(min(swmin[0], swmin[1]), min(swmin[2], swmin[3]));
        snv = nv;
        if (tgt_blk)
            for (int q = 0; q < nv; q++) swin[scell[q]] = (short)q;
    }
    __syncthreads();
    int nv = snv;

    // tconf_v (conf at object's own cell, anchor 0) — only in tgt blocks
    if (tgt_blk && tid < nv) {
        int r = scell[tid];
        const float* base = out + (size_t)b * NCH * NPIX + r;
        float ch[12];
        #pragma unroll
        for (int c = 0; c < 12; c++) ch[c] = base[(size_t)c * NPIX];
        float x0 = sigmoidf_fast(ch[0]);
        float y0 = sigmoidf_fast(ch[1]);
        const float SX = 640.f / 19.f, SY = 480.f / 19.f;
        float px[6], py[6];
        px[0] = (x0 + (float)gi) * SX;
        py[0] = (y0 + (float)gj) * SY;
        #pragma unroll
        for (int k = 1; k < 6; k++) {
            px[k] = fmaf(ch[2 * k],     SX, px[0]);
            py[k] = fmaf(ch[2 * k + 1], SY, py[0]);
        }
        float acc = 0.f;
        #pragma unroll
        for (int c = 0; c < 6; c++) {
            float dx = g[2 * c] * 640.f - px[c];
            float dy = g[2 * c + 1] * 480.f - py[c];
            float d2 = fmaf(dy, dy, dx * dx);
            if (d2 < 6400.f) {
                float dist = sqrt_approx(d2);
                acc += (__expf(fmaf(dist, -0.025f, 2.f)) - 1.f);
            }
        }
        stconf[tid] = acc * (INV_CONF0 / 6.f);
    }
    __syncthreads();

    // ---- per-anchor loss; warp -> (anchor, 8x4 cell tile) ----
    float lsum = 0.f;
    int W = bx * 4 + (tid >> 5);
    int lane = tid & 31;
    if (W < WPB) {
        int a  = W / TILES;
        int t  = W - a * TILES;
        int tx = t % 3;
        int ty = t / 3;
        int i  = tx * 8 + (lane & 7);
        int j  = ty * 4 + (lane >> 3);
        if (i < 19 && j < 19) {
            int r = j * 19 + i;
            const float* base = out + ((size_t)b * NCH + a * 26) * NPIX + r;
            float ch[13];
            #pragma unroll
            for (int c = 0; c < 13; c++) ch[c] = base[(size_t)c * NPIX];

            float x0 = sigmoidf_fast(ch[0]);
            float y0 = sigmoidf_fast(ch[1]);
            const float SX = 640.f / 19.f, SY = 480.f / 19.f;
            float px[6], py[6];
            px[0] = (x0 + (float)i) * SX;
            py[0] = (y0 + (float)j) * SY;
            #pragma unroll
            for (int k = 1; k < 6; k++) {
                px[k] = fmaf(ch[2 * k],     SX, px[0]);
                py[k] = fmaf(ch[2 * k + 1], SY, py[0]);
            }

            float m = 0.f;
            for (int q = 0; q < nv; q++) {
                float acc = 0.f;
                #pragma unroll
                for (int c = 0; c < 6; c++) {
                    float2 gc = sg[q * 6 + c];
                    float dx = gc.x - px[c];
                    float dy = gc.y - py[c];
                    float d2 = fmaf(dy, dy, dx * dx);
                    if (d2 < 6400.f) {
                        float dist = sqrt_approx(d2);
                        acc += (__expf(fmaf(dist, -0.025f, 2.f)) - 1.f);
                    }
                }
                m = fmaxf(m, acc);
            }
            m *= (INV_CONF0 / 6.f);

            float conf = sigmoidf_fast(ch[12]);
            float mask = (m < 0.4f) ? 1.f : 0.f;
            float tc = 0.f;

            if (a == 0) {
                int w = swin[r];
                if (w >= 0) {
                    mask = 5.f;
                    tc = stconf[w];
                    const float* tv = stv + w * 12;
                    float d0 = x0 - tv[0];
                    float d1 = y0 - tv[1];
                    float cs = fmaf(d1, d1, d0 * d0);
                    #pragma unroll
                    for (int k = 2; k < 12; k++) {
                        float d = ch[k] - tv[k];
                        cs = fmaf(d, d, cs);
                    }
                    lsum += 0.5f * cs;

                    const float* cbase = base + (size_t)13 * NPIX;
                    float lg[NCC];
                    float mx = -1e30f;
                    #pragma unroll
                    for (int c = 0; c < NCC; c++) {
                        lg[c] = cbase[(size_t)c * NPIX];
                        mx = fmaxf(mx, lg[c]);
                    }
                    float se = 0.f;
                    #pragma unroll
                    for (int c = 0; c < NCC; c++) se += __expf(lg[c] - mx);
                    lsum += mx + __logf(se) - lg[scls[w]];
                }
            }
            float cd = conf - tc;
            lsum += 0.5f * mask * cd * cd;
        }
    }

    // block reduce, then single-pass atomic finish
    #pragma unroll
    for (int off = 16; off > 0; off >>= 1)
        lsum += __shfl_down_sync(0xffffffffu, lsum, off);
    if ((tid & 31) == 0) swsum[tid >> 5] = lsum;
    __syncthreads();
    if (tid == 0) {
        double s = (double)swsum[0] + (double)swsum[1]
                 + (double)swsum[2] + (double)swsum[3];
        atomicAdd(&g_accum, s);
        __threadfence();
        int old = atomicAdd(&g_done, 1);
        if (old == n_blocks - 1) {
            d_out[0] = (float)g_accum;
            g_accum = 0.0;
            g_done = 0;
        }
    }
}

extern "C" void kernel_launch(void* const* d_in, const int* in_sizes, int n_in,
                              void* d_out, int out_size) {
    const float* out = (const float*)d_in[0];
    const float* tgt = (const float*)d_in[1];
    int nB = in_sizes[0] / (NCH * NPIX);

    dim3 grid(BLKS_PB, nB);
    fused_kernel<<<grid, 128>>>(out, tgt, (float*)d_out, BLKS_PB * nB);
}

// round 4
// speedup vs baseline: 1.6089x; 1.1603x over previous
#include <cuda_runtime.h>
#include <math.h>

#define NAA 5
#define NCC 13
#define NPIX 361
#define MAXOBJ 50
#define NCH 130          /* NA*(13+NC) */
#define TILES 15         /* 3 x-tiles(8) * 5 y-tiles(4) covering 19x19 */
#define BLKS_PB (NAA * TILES)   /* 75 blocks per batch */

__device__ double g_accum = 0.0;
__device__ int    g_done  = 0;

__device__ __forceinline__ float sigmoidf_fast(float x) {
    return __fdividef(1.f, 1.f + __expf(-x));
}
__device__ __forceinline__ float sqrt_approx(float x) {
    float r; asm("sqrt.approx.f32 %0, %1;" : "=f"(r) : "f"(x)); return r;
}

#define INV_CONF0 0.15651764274966568f   /* 1/(e^2-1) */

// grid = (75, nB), block = 128.  Block -> (anchor a, 8x4 cell tile t).
// Object loop split across the 4 warps; partial max combined through smem.
__global__ void __launch_bounds__(128) fused_kernel(const float* __restrict__ out,
                                                    const float* __restrict__ tgt,
                                                    float* __restrict__ d_out,
                                                    int n_blocks) {
    int b    = blockIdx.y;
    int bx   = blockIdx.x;
    int tid  = threadIdx.x;
    int w    = tid >> 5;
    int lane = tid & 31;
    int a    = bx / TILES;
    int t    = bx - a * TILES;
    bool tgt_blk = (a == 0);

    __shared__ float2 sg[MAXOBJ * 6];     // scaled object corners
    __shared__ float  stv[MAXOBJ * 12];   // coord targets      (a==0 only)
    __shared__ float  stconf[MAXOBJ];     //                    (a==0 only)
    __shared__ int    scls[MAXOBJ];       //                    (a==0 only)
    __shared__ int    scell[MAXOBJ];
    __shared__ short  swin[NPIX];         //                    (a==0 only)
    __shared__ int    snv;
    __shared__ int    swmin[4];
    __shared__ float  spart[128];         // per-warp partial max, per cell-lane

    if (tgt_blk)
        for (int c = tid; c < NPIX; c += 128) swin[c] = -1;

    // ---- per-block target prep ----
    float g[12];
    int gi = 0, gj = 0;
    bool has = (tid < MAXOBJ);
    if (has) {
        const float* row = tgt + (size_t)(b * MAXOBJ + tid) * 15;
        float cls = row[0];
        #pragma unroll
        for (int k = 0; k < 12; k++) g[k] = row[1 + k];
        gi = (int)floorf(g[0] * 19.f);
        gj = (int)floorf(g[1] * 19.f);
        scell[tid] = gj * 19 + gi;
        #pragma unroll
        for (int c = 0; c < 6; c++)
            sg[tid * 6 + c] = make_float2(g[2 * c] * 640.f, g[2 * c + 1] * 480.f);
        if (tgt_blk) {
            float* tv = stv + tid * 12;
            tv[0] = g[0] * 19.f - (float)gi;
            tv[1] = g[1] * 19.f - (float)gj;
            #pragma unroll
            for (int k = 1; k < 6; k++) {
                tv[2 * k]     = (g[2 * k]     - g[0]) * 19.f;
                tv[2 * k + 1] = (g[2 * k + 1] - g[1]) * 19.f;
            }
            scls[tid] = (int)cls;
        }
    }

    int cand = (has && g[0] == 0.f) ? tid : MAXOBJ;
    #pragma unroll
    for (int off = 16; off > 0; off >>= 1)
        cand = min(cand, __shfl_down_sync(0xffffffffu, cand, off));
    if (lane == 0) swmin[w] = cand;
    __syncthreads();
    if (tid == 0) {
        int nv = min(min(swmin[0], swmin[1]), min(swmin[2], swmin[3]));
        snv = nv;
        if (tgt_blk)
            for (int q = 0; q < nv; q++) swin[scell[q]] = (short)q;
    }
    __syncthreads();
    int nv = snv;

    // tconf_v (anchor-0 conf at each object's own cell) — a==0 blocks only
    if (tgt_blk && tid < nv) {
        int r = scell[tid];
        const float* base = out + (size_t)b * NCH * NPIX + r;
        float ch[12];
        #pragma unroll
        for (int c = 0; c < 12; c++) ch[c] = base[(size_t)c * NPIX];
        float x0 = sigmoidf_fast(ch[0]);
        float y0 = sigmoidf_fast(ch[1]);
        const float SX = 640.f / 19.f, SY = 480.f / 19.f;
        float px[6], py[6];
        px[0] = (x0 + (float)gi) * SX;
        py[0] = (y0 + (float)gj) * SY;
        #pragma unroll
        for (int k = 1; k < 6; k++) {
            px[k] = fmaf(ch[2 * k],     SX, px[0]);
            py[k] = fmaf(ch[2 * k + 1], SY, py[0]);
        }
        float acc = 0.f;
        #pragma unroll
        for (int c = 0; c < 6; c++) {
            float dx = g[2 * c] * 640.f - px[c];
            float dy = g[2 * c + 1] * 480.f - py[c];
            float d2 = fmaf(dy, dy, dx * dx);
            if (d2 < 6400.f) {
                float dist = sqrt_approx(d2);
                acc += (__expf(fmaf(dist, -0.025f, 2.f)) - 1.f);
            }
        }
        stconf[tid] = acc * (INV_CONF0 / 6.f);
    }
    __syncthreads();

    // ---- main: lane -> cell within the 8x4 tile; warp -> object subset ----
    int tx = t % 3, ty = t / 3;
    int i = tx * 8 + (lane & 7);
    int j = ty * 4 + (lane >> 3);
    bool active = (i < 19) && (j < 19);
    int r = j * 19 + i;

    const float* base = out + ((size_t)b * NCH + a * 26) * NPIX + r;
    float ch[12];
    float x0 = 0.f, y0 = 0.f;
    float px[6], py[6];
    if (active) {
        #pragma unroll
        for (int c = 0; c < 12; c++) ch[c] = base[(size_t)c * NPIX];
        x0 = sigmoidf_fast(ch[0]);
        y0 = sigmoidf_fast(ch[1]);
        const float SX = 640.f / 19.f, SY = 480.f / 19.f;
        px[0] = (x0 + (float)i) * SX;
        py[0] = (y0 + (float)j) * SY;
        #pragma unroll
        for (int k = 1; k < 6; k++) {
            px[k] = fmaf(ch[2 * k],     SX, px[0]);
            py[k] = fmaf(ch[2 * k + 1], SY, py[0]);
        }
    } else {
        #pragma unroll
        for (int k = 0; k < 6; k++) { px[k] = 1e9f; py[k] = 1e9f; }
    }

    float m = 0.f;
    for (int q = w; q < nv; q += 4) {
        float acc = 0.f;
        #pragma unroll
        for (int c = 0; c < 6; c++) {
            float2 gc = sg[q * 6 + c];
            float dx = gc.x - px[c];
            float dy = gc.y - py[c];
            float d2 = fmaf(dy, dy, dx * dx);
            if (d2 < 6400.f) {
                float dist = sqrt_approx(d2);
                acc += (__expf(fmaf(dist, -0.025f, 2.f)) - 1.f);
            }
        }
        m = fmaxf(m, acc);
    }
    spart[tid] = m;
    __syncthreads();

    // ---- warp 0: combine partials, compute losses ----
    float lsum = 0.f;
    if (w == 0 && active) {
        m = fmaxf(fmaxf(spart[lane], spart[32 + lane]),
                  fmaxf(spart[64 + lane], spart[96 + lane]));
        m *= (INV_CONF0 / 6.f);

        float conf = sigmoidf_fast(base[(size_t)12 * NPIX]);
        float mask = (m < 0.4f) ? 1.f : 0.f;
        float tc = 0.f;

        if (tgt_blk) {
            int win = swin[r];
            if (win >= 0) {
                mask = 5.f;   // OBJECT_SCALE
                tc = stconf[win];

                const float* tv = stv + win * 12;
                float d0 = x0 - tv[0];
                float d1 = y0 - tv[1];
                float cs = fmaf(d1, d1, d0 * d0);
                #pragma unroll
                for (int k = 2; k < 12; k++) {
                    float d = ch[k] - tv[k];
                    cs = fmaf(d, d, cs);
                }
                lsum += 0.5f * cs;

                const float* cbase = base + (size_t)13 * NPIX;
                float lg[NCC];
                float mx = -1e30f;
                #pragma unroll
                for (int c = 0; c < NCC; c++) {
                    lg[c] = cbase[(size_t)c * NPIX];
                    mx = fmaxf(mx, lg[c]);
                }
                float se = 0.f;
                #pragma unroll
                for (int c = 0; c < NCC; c++) se += __expf(lg[c] - mx);
                lsum += mx + __logf(se) - lg[scls[win]];
            }
        }
        float cd = conf - tc;
        lsum += 0.5f * mask * cd * cd;
    }

    if (w == 0) {
        #pragma unroll
        for (int off = 16; off > 0; off >>= 1)
            lsum += __shfl_down_sync(0xffffffffu, lsum, off);
        if (lane == 0) {
            atomicAdd(&g_accum, (double)lsum);
            __threadfence();
            int old = atomicAdd(&g_done, 1);
            if (old == n_blocks - 1) {
                d_out[0] = (float)g_accum;
                g_accum = 0.0;
                g_done = 0;
            }
        }
    }
}

extern "C" void kernel_launch(void* const* d_in, const int* in_sizes, int n_in,
                              void* d_out, int out_size) {
    const float* out = (const float*)d_in[0];
    const float* tgt = (const float*)d_in[1];
    int nB = in_sizes[0] / (NCH * NPIX);

    dim3 grid(BLKS_PB, nB);
    fused_kernel<<<grid, 128>>>(out, tgt, (float*)d_out, BLKS_PB * nB);
}

// round 5
// speedup vs baseline: 1.6127x; 1.0024x over previous
#include <cuda_runtime.h>
#include <math.h>

#define NAA 5
#define NCC 13
#define NPIX 361
#define MAXOBJ 50
#define NCH 130          /* NA*(13+NC) */
#define TILES 15         /* 3 x-tiles(8) * 5 y-tiles(4) covering 19x19 */
#define NTHR 160         /* 5 warps: warp = anchor */

__device__ double g_accum = 0.0;
__device__ int    g_done  = 0;

__device__ __forceinline__ float sigmoidf_fast(float x) {
    return __fdividef(1.f, 1.f + __expf(-x));
}
__device__ __forceinline__ float sqrt_approx(float x) {
    float r; asm("sqrt.approx.f32 %0, %1;" : "=f"(r) : "f"(x)); return r;
}
__device__ __forceinline__ float ex2_approx(float x) {
    float r; asm("ex2.approx.f32 %0, %1;" : "=f"(r) : "f"(x)); return r;
}

#define INV_CONF0 0.15651764274966568f   /* 1/(e^2-1) */
#define EK1 (-0.036067376f)              /* -0.025 * log2(e) */
#define EK0 (2.88539008f)                /*  2.0   * log2(e) */

// conf contribution of one corner (shared by both paths for consistency)
__device__ __forceinline__ void corner_acc(float dx, float dy, float& acc) {
    float d2 = fmaf(dy, dy, dx * dx);
    if (d2 < 6400.f)
        acc += ex2_approx(fmaf(sqrt_approx(d2), EK1, EK0)) - 1.f;
}

// grid = (15, nB), block = 160.  Block -> 8x4 cell tile; warp -> anchor.
__global__ void __launch_bounds__(NTHR) fused_kernel(const float* __restrict__ out,
                                                     const float* __restrict__ tgt,
                                                     float* __restrict__ d_out,
                                                     int n_warps) {
    int b    = blockIdx.y;
    int t    = blockIdx.x;
    int tid  = threadIdx.x;
    int a    = tid >> 5;        // warp = anchor
    int lane = tid & 31;

    __shared__ float  stg[MAXOBJ * 15];   // staged target rows (coalesced load)
    __shared__ float4 s4[MAXOBJ * 3];     // scaled corners, 2 per float4
    __shared__ float  stv[MAXOBJ * 12];   // coord targets
    __shared__ float  stconf[MAXOBJ];
    __shared__ int    scls[MAXOBJ];
    __shared__ int    scell[MAXOBJ];
    __shared__ int    swin[NPIX];
    __shared__ int    snv;

    // ---- phase 0: init + coalesced stage of target ----
    if (tid == 0) snv = MAXOBJ;
    for (int c = tid; c < NPIX; c += NTHR) swin[c] = -1;
    {
        const float* src = tgt + (size_t)b * (MAXOBJ * 15);
        #pragma unroll
        for (int k = 0; k < 5; k++) {
            int idx = tid + k * NTHR;
            if (idx < MAXOBJ * 15) stg[idx] = src[idx];
        }
    }
    __syncthreads();

    // ---- phase 1: parse objects from smem ----
    float g[12];
    int gi = 0, gj = 0;
    if (tid < MAXOBJ) {
        const float* row = stg + tid * 15;
        float cls = row[0];
        #pragma unroll
        for (int k = 0; k < 12; k++) g[k] = row[1 + k];
        gi = (int)floorf(g[0] * 19.f);
        gj = (int)floorf(g[1] * 19.f);
        scell[tid] = gj * 19 + gi;
        #pragma unroll
        for (int p = 0; p < 3; p++)
            s4[tid * 3 + p] = make_float4(g[4 * p]     * 640.f, g[4 * p + 1] * 480.f,
                                          g[4 * p + 2] * 640.f, g[4 * p + 3] * 480.f);
        float* tv = stv + tid * 12;
        tv[0] = g[0] * 19.f - (float)gi;
        tv[1] = g[1] * 19.f - (float)gj;
        #pragma unroll
        for (int k = 1; k < 6; k++) {
            tv[2 * k]     = (g[2 * k]     - g[0]) * 19.f;
            tv[2 * k + 1] = (g[2 * k + 1] - g[1]) * 19.f;
        }
        scls[tid] = (int)cls;
        if (g[0] == 0.f) atomicMin(&snv, tid);   // cumprod validity = first zero
    }
    __syncthreads();
    int nv = snv;

    // ---- phase 2: winner table (atomicMax == last-valid-writer wins) + tconf ----
    if (tid < nv) {
        atomicMax(&swin[scell[tid]], tid);

        int r = scell[tid];
        const float* base = out + (size_t)b * NCH * NPIX + r;   // anchor 0
        float ch[12];
        #pragma unroll
        for (int c = 0; c < 12; c++) ch[c] = base[(size_t)c * NPIX];
        float x0 = sigmoidf_fast(ch[0]);
        float y0 = sigmoidf_fast(ch[1]);
        const float SX = 640.f / 19.f, SY = 480.f / 19.f;
        float px[6], py[6];
        px[0] = (x0 + (float)gi) * SX;
        py[0] = (y0 + (float)gj) * SY;
        #pragma unroll
        for (int k = 1; k < 6; k++) {
            px[k] = fmaf(ch[2 * k],     SX, px[0]);
            py[k] = fmaf(ch[2 * k + 1], SY, py[0]);
        }
        float acc = 0.f;
        #pragma unroll
        for (int c = 0; c < 6; c++)
            corner_acc(g[2 * c] * 640.f - px[c], g[2 * c + 1] * 480.f - py[c], acc);
        stconf[tid] = acc * (INV_CONF0 / 6.f);
    }
    __syncthreads();

    // ---- phase 3: per-(anchor, cell) loss; warp owns its anchor ----
    int tx = t % 3, ty = t / 3;
    int i = tx * 8 + (lane & 7);
    int j = ty * 4 + (lane >> 3);
    bool active = (i < 19) && (j < 19);
    int r = j * 19 + i;

    const float* base = out + ((size_t)b * NCH + a * 26) * NPIX + r;
    float ch[12];
    float x0 = 0.f, y0 = 0.f;
    float px[6], py[6];
    if (active) {
        #pragma unroll
        for (int c = 0; c < 12; c++) ch[c] = base[(size_t)c * NPIX];
        x0 = sigmoidf_fast(ch[0]);
        y0 = sigmoidf_fast(ch[1]);
        const float SX = 640.f / 19.f, SY = 480.f / 19.f;
        px[0] = (x0 + (float)i) * SX;
        py[0] = (y0 + (float)j) * SY;
        #pragma unroll
        for (int k = 1; k < 6; k++) {
            px[k] = fmaf(ch[2 * k],     SX, px[0]);
            py[k] = fmaf(ch[2 * k + 1], SY, py[0]);
        }
    } else {
        #pragma unroll
        for (int k = 0; k < 6; k++) { px[k] = 1e9f; py[k] = 1e9f; }
    }

    float m = 0.f;
    const float4* op = s4;
    for (int q = 0; q < nv; q++, op += 3) {
        float acc = 0.f;
        #pragma unroll
        for (int p = 0; p < 3; p++) {
            float4 v = op[p];
            corner_acc(v.x - px[2 * p],     v.y - py[2 * p],     acc);
            corner_acc(v.z - px[2 * p + 1], v.w - py[2 * p + 1], acc);
        }
        m = fmaxf(m, acc);
    }

    float lsum = 0.f;
    if (active) {
        m *= (INV_CONF0 / 6.f);
        float conf = sigmoidf_fast(base[(size_t)12 * NPIX]);
        float mask = (m < 0.4f) ? 1.f : 0.f;
        float tc = 0.f;

        if (a == 0) {
            int win = swin[r];
            if (win >= 0) {
                mask = 5.f;   // OBJECT_SCALE
                tc = stconf[win];

                const float* tv = stv + win * 12;
                float d0 = x0 - tv[0];
                float d1 = y0 - tv[1];
                float cs = fmaf(d1, d1, d0 * d0);
                #pragma unroll
                for (int k = 2; k < 12; k++) {
                    float d = ch[k] - tv[k];
                    cs = fmaf(d, d, cs);
                }
                lsum += 0.5f * cs;

                const float* cbase = base + (size_t)13 * NPIX;
                float lg[NCC];
                float mx = -1e30f;
                #pragma unroll
                for (int c = 0; c < NCC; c++) {
                    lg[c] = cbase[(size_t)c * NPIX];
                    mx = fmaxf(mx, lg[c]);
                }
                float se = 0.f;
                #pragma unroll
                for (int c = 0; c < NCC; c++) se += __expf(lg[c] - mx);
                lsum += mx + __logf(se) - lg[scls[win]];
            }
        }
        float cd = conf - tc;
        lsum += 0.5f * mask * cd * cd;
    }

    // warp reduce; one atomic per warp
    #pragma unroll
    for (int off = 16; off > 0; off >>= 1)
        lsum += __shfl_down_sync(0xffffffffu, lsum, off);
    if (lane == 0) {
        atomicAdd(&g_accum, (double)lsum);
        __threadfence();
        int old = atomicAdd(&g_done, 1);
        if (old == n_warps - 1) {
            d_out[0] = (float)g_accum;
            g_accum = 0.0;
            g_done = 0;
        }
    }
}

extern "C" void kernel_launch(void* const* d_in, const int* in_sizes, int n_in,
                              void* d_out, int out_size) {
    const float* out = (const float*)d_in[0];
    const float* tgt = (const float*)d_in[1];
    int nB = in_sizes[0] / (NCH * NPIX);

    dim3 grid(TILES, nB);
    fused_kernel<<<grid, NTHR>>>(out, tgt, (float*)d_out, TILES * nB * NAA);
}